// round 12
// baseline (speedup 1.0000x reference)
#include <cuda_runtime.h>

#define NPTS   65536     // B*T
#define TPB    256
#define P      4
#define GPB    64        // groups per block (4 lanes each)
#define PPB    256       // points per MLP block
#define NBLKS  (NPTS/PPB)

typedef unsigned long long u64;

__device__ __align__(16) float g_cf[NPTS * 32];   // 8MB scratch: gathered features

__device__ __forceinline__ u64 pk2(float a, float b) {
    u64 r; asm("mov.b64 %0, {%1,%2};" : "=l"(r) : "f"(a), "f"(b)); return r;
}
__device__ __forceinline__ u64 dup2(float a) { return pk2(a, a); }
__device__ __forceinline__ void upk2(u64 v, float& a, float& b) {
    asm("mov.b64 {%0,%1}, %2;" : "=f"(a), "=f"(b) : "l"(v));
}
__device__ __forceinline__ void fma2(u64& d, u64 a, u64 b) {
    asm("fma.rn.f32x2 %0, %1, %2, %0;" : "+l"(d) : "l"(a), "l"(b));
}
__device__ __forceinline__ u64 add2(u64 a, u64 b) {
    u64 r; asm("add.rn.f32x2 %0, %1, %2;" : "=l"(r) : "l"(a), "l"(b)); return r;
}

// ============================ kernel 1: gather ============================
__global__ __launch_bounds__(256)
void gather_kernel(
    const float* __restrict__ p,      // [16,4096,3]
    const float* __restrict__ c,      // [16,4,128,128,32]
    const float* __restrict__ Cmat)   // [16,4,4,3]
{
    __shared__ float sC[32];          // [4 views][8]: c00..c12, inv_den

    const int tid = threadIdx.x;
    const int q4  = tid & 3;
    const int pt  = blockIdx.x * 64 + (tid >> 2);
    const int b   = pt >> 12;

    if (tid < 28) {
        int l = tid / 7, k = tid % 7;
        const float* Cb = Cmat + (b * 4 + l) * 12;
        sC[l * 8 + k] = (k < 6) ? Cb[k] : (1.0f / (Cb[9] + 0.05f));
    }
    __syncthreads();

    const float p0 = p[pt * 3 + 0];
    const float p1 = p[pt * 3 + 1];
    const float p2 = p[pt * 3 + 2];
    const float ps0 = p0 / 0.55f;
    const float ps1 = p1 / 0.55f;
    const float ps2 = p2 / 0.55f;

    u64 cf2[4];
    #pragma unroll
    for (int m = 0; m < 4; m++) cf2[m] = 0ull;

    #pragma unroll
    for (int l = 0; l < 4; l++) {
        const float c00 = sC[l*8 + 0], c01 = sC[l*8 + 1], c02 = sC[l*8 + 2];
        const float c10 = sC[l*8 + 3], c11 = sC[l*8 + 4], c12 = sC[l*8 + 5];
        const float rden = sC[l*8 + 6];

        const float px = (c00 * ps0 + c01 * ps1 + c02 * ps2) * rden;
        const float py = (c10 * ps0 + c11 * ps1 + c12 * ps2) * rden;

        float xg = fmaf(px, 63.5f, 63.5f);   // (px + 1) / (2/127)
        float yg = fmaf(py, 63.5f, 63.5f);
        xg = (xg >= 127.0f) ? 126.9f : xg;  xg = (xg < 0.0f) ? 0.0f : xg;
        yg = (yg >= 127.0f) ? 126.9f : yg;  yg = (yg < 0.0f) ? 0.0f : yg;

        // half-to-even rounding, same as jnp.round
        const float xl = rintf(xg - 0.5f), xr = rintf(xg + 0.5f);
        const float yl = rintf(yg - 0.5f), yh = rintf(yg + 0.5f);
        const int xil = (int)xl, xir = (int)xr;
        const int yil = (int)yl, yih = (int)yh;

        const float dx = xr - xg, dy = yh - yg;
        const u64 W11 = dup2(dx * dy);
        const u64 W12 = dup2((1.0f - dx) * dy);
        const u64 W21 = dup2(dx * (1.0f - dy));
        const u64 W22 = dup2((1.0f - dx) * (1.0f - dy));

        const int base = (b * 4 + l) * 128 * 128;
        const ulonglong2* r11 = (const ulonglong2*)(c + (size_t)(base + xil * 128 + yil) * 32) + q4 * 2;
        const ulonglong2* r12 = (const ulonglong2*)(c + (size_t)(base + xir * 128 + yil) * 32) + q4 * 2;
        const ulonglong2* r21 = (const ulonglong2*)(c + (size_t)(base + xil * 128 + yih) * 32) + q4 * 2;
        const ulonglong2* r22 = (const ulonglong2*)(c + (size_t)(base + xir * 128 + yih) * 32) + q4 * 2;

        #pragma unroll
        for (int q = 0; q < 2; q++) {
            const ulonglong2 a  = r11[q];
            const ulonglong2 e  = r12[q];
            const ulonglong2 f  = r21[q];
            const ulonglong2 gg = r22[q];
            fma2(cf2[2*q    ], W11, a.x);   fma2(cf2[2*q + 1], W11, a.y);
            fma2(cf2[2*q    ], W12, e.x);   fma2(cf2[2*q + 1], W12, e.y);
            fma2(cf2[2*q    ], W21, f.x);   fma2(cf2[2*q + 1], W21, f.y);
            fma2(cf2[2*q    ], W22, gg.x);  fma2(cf2[2*q + 1], W22, gg.y);
        }
    }

    ulonglong2* dst = (ulonglong2*)(g_cf + (size_t)pt * 32 + q4 * 8);
    dst[0] = make_ulonglong2(cf2[0], cf2[1]);
    dst[1] = make_ulonglong2(cf2[2], cf2[3]);
}

// ============================ kernel 2: MLP ============================
// smem float-offsets
#define OWS 0          // staged weights for current blk: W0 (1024) + W1 (1024)
#define OB0 2048       // 160
#define OB1 2208       // 160
#define OWP 2368       // 96
#define OBP 2464       // 32
#define OWO 2496       // 32
#define OBO 2528       // 1 (pad to 2544)
#define OXB 2544       // activation park: P x 64 groups x 36 floats
#define XSTR 36        // padded stride (bank-conflict-free group broadcast)
#define SMEM_BYTES ((OXB + P*GPB*XSTR) * 4)   // 47040 B -> 3 blocks/SM

__global__ __launch_bounds__(TPB, 3)
void mlp_kernel(
    const float* __restrict__ p,      // [16,4096,3]
    const float* __restrict__ fcpW,   // [3,32]
    const float* __restrict__ fcpb,   // [32]
    const float* __restrict__ W0,     // [5,32,32]
    const float* __restrict__ b0,     // [5,32]
    const float* __restrict__ W1,     // [5,32,32]
    const float* __restrict__ b1,     // [5,32]
    const float* __restrict__ Wout,   // [32,1]
    const float* __restrict__ bout,   // [1]
    float* __restrict__ out)          // [16,4096]
{
    extern __shared__ float sm[];

    const int tid = threadIdx.x;
    const int q4  = tid & 3;                      // channel quarter: ch [q4*8, q4*8+8)
    const int g   = tid >> 2;                     // group id 0..63
    const int pt0 = blockIdx.x * PPB + g;
    const int chb = q4 * 8;
    const unsigned FULL = 0xffffffffu;

    // ---- stage small constants once ----
    if (tid < 160) { sm[OB0 + tid] = b0[tid]; sm[OB1 + tid] = b1[tid]; }
    if (tid < 96) sm[OWP + tid] = fcpW[tid];
    if (tid < 32) { sm[OBP + tid] = fcpb[tid]; sm[OWO + tid] = Wout[tid]; }
    if (tid == 0) sm[OBO] = bout[0];
    __syncthreads();

    // ---- fc_p for P points (x carried in regs between blocks) ----
    float x[P][8];
    #pragma unroll
    for (int pp = 0; pp < P; pp++) {
        const int pt = pt0 + pp * GPB;
        const float p0 = p[pt * 3 + 0];
        const float p1 = p[pt * 3 + 1];
        const float p2 = p[pt * 3 + 2];
        #pragma unroll
        for (int j = 0; j < 8; j++) {
            const int ch = chb + j;
            float v = sm[OBP + ch];
            v = fmaf(p0, sm[OWP + ch],      v);
            v = fmaf(p1, sm[OWP + 32 + ch], v);
            v = fmaf(p2, sm[OWP + 64 + ch], v);
            x[pp][j] = v;
        }
    }

    float* const xb = sm + OXB;

    // ---- 5 resnet blocks; weights staged per block; cf re-read from L2 ----
    #pragma unroll 1
    for (int blk = 0; blk < 5; blk++) {
        __syncthreads();   // prev iter's weight/park reads complete

        // stage this block's W0|W1 (8KB from L2)
        #pragma unroll
        for (int i = tid; i < 2048; i += TPB)
            sm[OWS + i] = (i < 1024) ? W0[blk * 1024 + i] : W1[blk * 1024 + i - 1024];

        // cf add (from global scratch) + park RAW x; x regs dead after this
        #pragma unroll
        for (int pp = 0; pp < P; pp++) {
            const int pt = pt0 + pp * GPB;
            const ulonglong2* src = (const ulonglong2*)(g_cf + (size_t)pt * 32 + chb);
            const ulonglong2 ca = src[0], cb = src[1];
            float c0, c1, c2, c3;
            upk2(ca.x, c0, c1); upk2(ca.y, c2, c3);
            x[pp][0] += c0; x[pp][1] += c1; x[pp][2] += c2; x[pp][3] += c3;
            upk2(cb.x, c0, c1); upk2(cb.y, c2, c3);
            x[pp][4] += c0; x[pp][5] += c1; x[pp][6] += c2; x[pp][7] += c3;

            float* dst = xb + (pp * GPB + g) * XSTR + chb;
            *(float4*)(dst)     = make_float4(x[pp][0], x[pp][1], x[pp][2], x[pp][3]);
            *(float4*)(dst + 4) = make_float4(x[pp][4], x[pp][5], x[pp][6], x[pp][7]);
        }
        __syncthreads();   // weights + parks visible

        // ---- h = relu(x) @ W0 + b0  (x read from park, fmax on read) ----
        u64 acc[P][4];
        {
            const ulonglong2* bb = (const ulonglong2*)(sm + OB0 + blk * 32 + chb);
            const ulonglong2 b01 = bb[0], b23 = bb[1];
            #pragma unroll
            for (int pp = 0; pp < P; pp++) {
                acc[pp][0] = b01.x; acc[pp][1] = b01.y;
                acc[pp][2] = b23.x; acc[pp][3] = b23.y;
            }
        }
        {
            const float* wbase = sm + OWS + chb;
            #pragma unroll
            for (int kc = 0; kc < 8; kc++) {
                float4 xr[P];
                #pragma unroll
                for (int pp = 0; pp < P; pp++)
                    xr[pp] = *(const float4*)(xb + (pp * GPB + g) * XSTR + kc * 4);
                ulonglong2 w[4][2];
                #pragma unroll
                for (int i = 0; i < 4; i++) {
                    const ulonglong2* r = (const ulonglong2*)(wbase + (kc*4 + i) * 32);
                    w[i][0] = r[0]; w[i][1] = r[1];
                }
                #pragma unroll
                for (int pp = 0; pp < P; pp++) {
                    u64 vv;
                    vv = dup2(fmaxf(xr[pp].x, 0.0f));
                    fma2(acc[pp][0], vv, w[0][0].x); fma2(acc[pp][1], vv, w[0][0].y);
                    fma2(acc[pp][2], vv, w[0][1].x); fma2(acc[pp][3], vv, w[0][1].y);
                    vv = dup2(fmaxf(xr[pp].y, 0.0f));
                    fma2(acc[pp][0], vv, w[1][0].x); fma2(acc[pp][1], vv, w[1][0].y);
                    fma2(acc[pp][2], vv, w[1][1].x); fma2(acc[pp][3], vv, w[1][1].y);
                    vv = dup2(fmaxf(xr[pp].z, 0.0f));
                    fma2(acc[pp][0], vv, w[2][0].x); fma2(acc[pp][1], vv, w[2][0].y);
                    fma2(acc[pp][2], vv, w[2][1].x); fma2(acc[pp][3], vv, w[2][1].y);
                    vv = dup2(fmaxf(xr[pp].w, 0.0f));
                    fma2(acc[pp][0], vv, w[3][0].x); fma2(acc[pp][1], vv, w[3][0].y);
                    fma2(acc[pp][2], vv, w[3][1].x); fma2(acc[pp][3], vv, w[3][1].y);
                }
            }
        }

        // ---- init x_new = x_cf + b1 from raw park (before h overwrites buffer) ----
        u64 xp[P][4];
        {
            const ulonglong2* bb = (const ulonglong2*)(sm + OB1 + blk * 32 + chb);
            const ulonglong2 b01 = bb[0], b23 = bb[1];
            #pragma unroll
            for (int pp = 0; pp < P; pp++) {
                const ulonglong2* src = (const ulonglong2*)(xb + (pp * GPB + g) * XSTR + chb);
                const ulonglong2 pa = src[0], pb = src[1];
                xp[pp][0] = add2(pa.x, b01.x);
                xp[pp][1] = add2(pa.y, b01.y);
                xp[pp][2] = add2(pb.x, b23.x);
                xp[pp][3] = add2(pb.y, b23.y);
            }
        }
        __syncwarp(FULL);   // all x-park reads done (park rows are warp-private)

        // park RAW h (relu applied on read); acc regs dead after this
        #pragma unroll
        for (int pp = 0; pp < P; pp++) {
            float h0,h1,h2,h3,h4,h5,h6,h7;
            upk2(acc[pp][0], h0, h1); upk2(acc[pp][1], h2, h3);
            upk2(acc[pp][2], h4, h5); upk2(acc[pp][3], h6, h7);
            float* dst = xb + (pp * GPB + g) * XSTR + chb;
            *(float4*)(dst)     = make_float4(h0, h1, h2, h3);
            *(float4*)(dst + 4) = make_float4(h4, h5, h6, h7);
        }
        __syncwarp(FULL);

        // ---- x_new += relu(h) @ W1 ----
        {
            const float* wbase = sm + OWS + 1024 + chb;
            #pragma unroll
            for (int kc = 0; kc < 8; kc++) {
                float4 hr[P];
                #pragma unroll
                for (int pp = 0; pp < P; pp++)
                    hr[pp] = *(const float4*)(xb + (pp * GPB + g) * XSTR + kc * 4);
                ulonglong2 w[4][2];
                #pragma unroll
                for (int i = 0; i < 4; i++) {
                    const ulonglong2* r = (const ulonglong2*)(wbase + (kc*4 + i) * 32);
                    w[i][0] = r[0]; w[i][1] = r[1];
                }
                #pragma unroll
                for (int pp = 0; pp < P; pp++) {
                    u64 vv;
                    vv = dup2(fmaxf(hr[pp].x, 0.0f));
                    fma2(xp[pp][0], vv, w[0][0].x); fma2(xp[pp][1], vv, w[0][0].y);
                    fma2(xp[pp][2], vv, w[0][1].x); fma2(xp[pp][3], vv, w[0][1].y);
                    vv = dup2(fmaxf(hr[pp].y, 0.0f));
                    fma2(xp[pp][0], vv, w[1][0].x); fma2(xp[pp][1], vv, w[1][0].y);
                    fma2(xp[pp][2], vv, w[1][1].x); fma2(xp[pp][3], vv, w[1][1].y);
                    vv = dup2(fmaxf(hr[pp].z, 0.0f));
                    fma2(xp[pp][0], vv, w[2][0].x); fma2(xp[pp][1], vv, w[2][0].y);
                    fma2(xp[pp][2], vv, w[2][1].x); fma2(xp[pp][3], vv, w[2][1].y);
                    vv = dup2(fmaxf(hr[pp].w, 0.0f));
                    fma2(xp[pp][0], vv, w[3][0].x); fma2(xp[pp][1], vv, w[3][0].y);
                    fma2(xp[pp][2], vv, w[3][1].x); fma2(xp[pp][3], vv, w[3][1].y);
                }
            }
        }
        #pragma unroll
        for (int pp = 0; pp < P; pp++) {
            upk2(xp[pp][0], x[pp][0], x[pp][1]);
            upk2(xp[pp][1], x[pp][2], x[pp][3]);
            upk2(xp[pp][2], x[pp][4], x[pp][5]);
            upk2(xp[pp][3], x[pp][6], x[pp][7]);
        }
    }

    // ---- output head ----
    const float sbo = sm[OBO];
    #pragma unroll
    for (int pp = 0; pp < P; pp++) {
        float acc = 0.0f;
        #pragma unroll
        for (int j = 0; j < 8; j++)
            acc = fmaf(fmaxf(x[pp][j], 0.0f), sm[OWO + chb + j], acc);
        acc += __shfl_xor_sync(FULL, acc, 1);
        acc += __shfl_xor_sync(FULL, acc, 2);
        if (q4 == 0) out[pt0 + pp * GPB] = acc + sbo;
    }
}

extern "C" void kernel_launch(void* const* d_in, const int* in_sizes, int n_in,
                              void* d_out, int out_size)
{
    const float* p    = (const float*)d_in[0];
    // d_in[1] = z (unused by the reference graph)
    const float* c    = (const float*)d_in[2];
    const float* Cm   = (const float*)d_in[3];
    const float* fpW  = (const float*)d_in[4];
    const float* fpb  = (const float*)d_in[5];
    const float* W0   = (const float*)d_in[6];
    const float* b0   = (const float*)d_in[7];
    const float* W1   = (const float*)d_in[8];
    const float* b1   = (const float*)d_in[9];
    const float* Wo   = (const float*)d_in[10];
    const float* bo   = (const float*)d_in[11];
    float* out = (float*)d_out;

    gather_kernel<<<NPTS / 64, 256>>>(p, c, Cm);

    cudaFuncSetAttribute(mlp_kernel,
                         cudaFuncAttributeMaxDynamicSharedMemorySize, SMEM_BYTES);
    mlp_kernel<<<NBLKS, TPB, SMEM_BYTES>>>(p, fpW, fpb, W0, b0, W1, b1, Wo, bo, out);
}